// round 1
// baseline (speedup 1.0000x reference)
#include <cuda_runtime.h>
#include <math.h>

#define BB 2
#define SS 2048
#define HH 16
#define DM 1024
#define DH 192
#define NQKV 9216
#define DL 3072
#define BHN 32
#define MROWS 4096

// Scratch (device globals: no allocation allowed)
__device__ float g_h[MROWS * DH];                 // 3 MB
__device__ float g_q[BHN * DH * SS];              // 50 MB, layout [bh][d][s]
__device__ float g_k[BHN * DH * SS];
__device__ float g_v[BHN * DH * SS];
__device__ float g_attn[MROWS * DL];              // 50 MB, layout [b*S+s][h*192+d]

// ---------------------------------------------------------------------------
// Kernel 1: h = rmsnorm(x @ w_down) * rms_w      [4096,1024]@[1024,192]
// One block = 16 rows, 192 threads (one per output column).
// ---------------------------------------------------------------------------
__global__ void k_down_rms(const float* __restrict__ x,
                           const float* __restrict__ w_down,
                           const float* __restrict__ rms_w) {
    extern __shared__ float sm[];
    float* xs  = sm;                  // 16*1024
    float* red = sm + 16 * 1024;      // 16*192
    float* rs  = red + 16 * 192;      // 16

    int t  = threadIdx.x;             // 0..191
    int m0 = blockIdx.x * 16;

    const float4* xin = (const float4*)(x + (size_t)m0 * DM);
    float4* xs4 = (float4*)xs;
    for (int i = t; i < 16 * DM / 4; i += 192) xs4[i] = xin[i];
    __syncthreads();

    float acc[16];
#pragma unroll
    for (int r = 0; r < 16; r++) acc[r] = 0.f;

    for (int k = 0; k < DM; k += 4) {
        float w0 = w_down[(k + 0) * DH + t];
        float w1 = w_down[(k + 1) * DH + t];
        float w2 = w_down[(k + 2) * DH + t];
        float w3 = w_down[(k + 3) * DH + t];
#pragma unroll
        for (int r = 0; r < 16; r++) {
            float4 xv = *(const float4*)&xs[r * DM + k];
            acc[r] += xv.x * w0 + xv.y * w1 + xv.z * w2 + xv.w * w3;
        }
    }

#pragma unroll
    for (int r = 0; r < 16; r++) red[r * 192 + t] = acc[r] * acc[r];
    __syncthreads();
    for (int st = 96; st >= 3; st >>= 1) {
        if (t < st) {
#pragma unroll
            for (int r = 0; r < 16; r++) red[r * 192 + t] += red[r * 192 + t + st];
        }
        __syncthreads();
    }
    if (t < 16) {
        float s3 = red[t * 192 + 0] + red[t * 192 + 1] + red[t * 192 + 2];
        rs[t] = rsqrtf(s3 / 192.0f + 1e-6f);
    }
    __syncthreads();

    float w = rms_w[t];
#pragma unroll
    for (int r = 0; r < 16; r++)
        g_h[(size_t)(m0 + r) * DH + t] = acc[r] * rs[r] * w;
}

// ---------------------------------------------------------------------------
// Kernel 2: qkv = h @ w_up, scattered into g_q/g_k/g_v [bh][d][s] layout.
// Tile 64(m) x 64(n), K=192 full. 256 threads, 4x4 microtile.
// tx -> m quad (writes coalesced along s), ty -> n quad.
// ---------------------------------------------------------------------------
__global__ void k_qkv(const float* __restrict__ w_up) {
    extern __shared__ float sm[];
    float* As = sm;                    // 192 * 68
    float* Bs = sm + 192 * 68;         // 192 * 64

    int tid = threadIdx.x;
    int tx = tid & 15, ty = tid >> 4;
    int m0 = blockIdx.x * 64;
    int n0 = blockIdx.y * 64;

    for (int i = tid; i < 64 * 192; i += 256) {
        int m = i / 192, k = i % 192;
        As[k * 68 + m] = g_h[(size_t)(m0 + m) * DH + k];
    }
    for (int i = tid; i < 192 * 64; i += 256) {
        int k = i >> 6, n = i & 63;
        Bs[k * 64 + n] = w_up[(size_t)k * NQKV + n0 + n];
    }
    __syncthreads();

    float acc[4][4];                   // [j(n)][i(m)]
#pragma unroll
    for (int j = 0; j < 4; j++)
#pragma unroll
        for (int i = 0; i < 4; i++) acc[j][i] = 0.f;

#pragma unroll 4
    for (int k = 0; k < 192; k++) {
        float4 a = *(const float4*)&As[k * 68 + tx * 4];
        float4 b = *(const float4*)&Bs[k * 64 + ty * 4];
        acc[0][0] += b.x * a.x; acc[0][1] += b.x * a.y; acc[0][2] += b.x * a.z; acc[0][3] += b.x * a.w;
        acc[1][0] += b.y * a.x; acc[1][1] += b.y * a.y; acc[1][2] += b.y * a.z; acc[1][3] += b.y * a.w;
        acc[2][0] += b.z * a.x; acc[2][1] += b.z * a.y; acc[2][2] += b.z * a.z; acc[2][3] += b.z * a.w;
        acc[3][0] += b.w * a.x; acc[3][1] += b.w * a.y; acc[3][2] += b.w * a.z; acc[3][3] += b.w * a.w;
    }

    int b_ = m0 >> 11;
    int s0 = m0 & 2047;
#pragma unroll
    for (int j = 0; j < 4; j++) {
        int n = n0 + ty * 4 + j;
        int ten = n / 3072;
        int l = n % 3072;
        int h_ = l & 15;
        int d  = l >> 4;
        float* dst = (ten == 0) ? g_q : ((ten == 1) ? g_k : g_v);
        float4 v4 = make_float4(acc[j][0], acc[j][1], acc[j][2], acc[j][3]);
        *(float4*)&dst[((size_t)(b_ * HH + h_) * DH + d) * SS + s0 + tx * 4] = v4;
    }
}

// ---------------------------------------------------------------------------
// Kernel 3: partial RoPE on q and k (first 32 of the 64 rope dims).
// grid (S/256, 16 pairs, 64 = {q,k} x 32 bh)
// ---------------------------------------------------------------------------
__global__ void k_rope() {
    int s = blockIdx.x * 256 + threadIdx.x;
    int p = blockIdx.y;                  // pair 0..15
    int z = blockIdx.z;                  // 0..63
    float* t = (z < 32) ? g_q : g_k;
    int bh = z & 31;

    float inv = (float)exp(-(double)(2 * p) / 32.0 * 9.210340371976184); // ln(10000)
    float ang = (float)s * inv;
    float c = cosf(ang), sn = sinf(ang);

    size_t i1 = ((size_t)bh * DH + 128 + 2 * p) * SS + s;
    size_t i2 = i1 + SS;
    float x1 = t[i1], x2 = t[i2];
    t[i1] = x1 * c - x2 * sn;
    t[i2] = x2 * c + x1 * sn;
}

// ---------------------------------------------------------------------------
// Kernel 4: causal flash attention per (bh, 64-query tile).
// Q/K tiles [192][64], V tile [192][65], P [64][68] (i-major).
// Threads (tx,ty)=16x16: scores i=ty*4, j=tx*4; PV i=ty*4, d=tx*12.
// ---------------------------------------------------------------------------
__global__ void __launch_bounds__(256, 1) k_attn() {
    extern __shared__ float sm[];
    float* Qs   = sm;                    // 192*64 = 12288
    float* Ks   = Qs + 12288;            // 12288
    float* Vs   = Ks + 12288;            // 192*65 = 12480
    float* Ps   = Vs + 12480;            // 64*68 = 4352
    float* rowm = Ps + 4352;             // 64
    float* rowl = rowm + 64;             // 64
    float* rowc = rowl + 64;             // 64

    int tid = threadIdx.x;
    int tx = tid & 15, ty = tid >> 4;
    int lane = tid & 31, warp = tid >> 5;

    int bh = blockIdx.y;
    int it = (gridDim.x - 1) - blockIdx.x;   // longest tiles scheduled first
    int i0 = it * 64;

    const float* qg = g_q + (size_t)bh * DH * SS;
    const float* kg = g_k + (size_t)bh * DH * SS;
    const float* vg = g_v + (size_t)bh * DH * SS;

    for (int idx = tid; idx < 192 * 16; idx += 256) {
        int k = idx >> 4, iv = idx & 15;
        *(float4*)&Qs[k * 64 + iv * 4] = *(const float4*)&qg[(size_t)k * SS + i0 + iv * 4];
    }
    if (tid < 64) { rowm[tid] = -1e30f; rowl[tid] = 0.f; }

    float o[4][12];
#pragma unroll
    for (int i = 0; i < 4; i++)
#pragma unroll
        for (int d = 0; d < 12; d++) o[i][d] = 0.f;

    const float scale = 0.07216878364870323f;   // 1/sqrt(192)

    for (int j0 = 0; j0 <= i0; j0 += 64) {
        __syncthreads();
        for (int idx = tid; idx < 192 * 16; idx += 256) {
            int k = idx >> 4, jv = idx & 15;
            *(float4*)&Ks[k * 64 + jv * 4] = *(const float4*)&kg[(size_t)k * SS + j0 + jv * 4];
        }
        for (int idx = tid; idx < 192 * 64; idx += 256) {
            int d = idx >> 6, j = idx & 63;
            Vs[d * 65 + j] = vg[(size_t)d * SS + j0 + j];
        }
        __syncthreads();

        // S = Q^T K  (i = ty*4+ii, j = tx*4+jj)
        float sc[4][4];
#pragma unroll
        for (int ii = 0; ii < 4; ii++)
#pragma unroll
            for (int jj = 0; jj < 4; jj++) sc[ii][jj] = 0.f;

#pragma unroll 4
        for (int k = 0; k < 192; k++) {
            float4 q  = *(const float4*)&Qs[k * 64 + ty * 4];
            float4 kv = *(const float4*)&Ks[k * 64 + tx * 4];
            sc[0][0] += q.x * kv.x; sc[0][1] += q.x * kv.y; sc[0][2] += q.x * kv.z; sc[0][3] += q.x * kv.w;
            sc[1][0] += q.y * kv.x; sc[1][1] += q.y * kv.y; sc[1][2] += q.y * kv.z; sc[1][3] += q.y * kv.w;
            sc[2][0] += q.z * kv.x; sc[2][1] += q.z * kv.y; sc[2][2] += q.z * kv.z; sc[2][3] += q.z * kv.w;
            sc[3][0] += q.w * kv.x; sc[3][1] += q.w * kv.y; sc[3][2] += q.w * kv.z; sc[3][3] += q.w * kv.w;
        }

#pragma unroll
        for (int ii = 0; ii < 4; ii++) {
            int gi = i0 + ty * 4 + ii;
            float4 v4;
            float* pv = (float*)&v4;
#pragma unroll
            for (int jj = 0; jj < 4; jj++) {
                float val = sc[ii][jj] * scale;
                if (j0 + tx * 4 + jj > gi) val = -1e9f;
                pv[jj] = val;
            }
            *(float4*)&Ps[(ty * 4 + ii) * 68 + tx * 4] = v4;
        }
        __syncthreads();

        // online softmax row stats: warp handles 8 rows
        for (int rr = 0; rr < 8; rr++) {
            int i = warp * 8 + rr;
            float v0 = Ps[i * 68 + lane];
            float v1 = Ps[i * 68 + 32 + lane];
            float mx = fmaxf(v0, v1);
#pragma unroll
            for (int off = 16; off > 0; off >>= 1)
                mx = fmaxf(mx, __shfl_xor_sync(0xffffffffu, mx, off));
            float oldm = rowm[i];
            float nm = fmaxf(oldm, mx);
            float e0 = __expf(v0 - nm);
            float e1 = __expf(v1 - nm);
            Ps[i * 68 + lane] = e0;
            Ps[i * 68 + 32 + lane] = e1;
            float sme = e0 + e1;
#pragma unroll
            for (int off = 16; off > 0; off >>= 1)
                sme += __shfl_xor_sync(0xffffffffu, sme, off);
            if (lane == 0) {
                float c = __expf(oldm - nm);
                rowc[i] = c;
                rowl[i] = rowl[i] * c + sme;
                rowm[i] = nm;
            }
        }
        __syncthreads();

        // rescale O, then O += P @ V^T   (i = ty*4+ii, d = tx*12+dd)
#pragma unroll
        for (int ii = 0; ii < 4; ii++) {
            float c = rowc[ty * 4 + ii];
#pragma unroll
            for (int dd = 0; dd < 12; dd++) o[ii][dd] *= c;
        }
#pragma unroll 2
        for (int j = 0; j < 64; j++) {
            float p0 = Ps[(ty * 4 + 0) * 68 + j];
            float p1 = Ps[(ty * 4 + 1) * 68 + j];
            float p2 = Ps[(ty * 4 + 2) * 68 + j];
            float p3 = Ps[(ty * 4 + 3) * 68 + j];
            float vv[12];
#pragma unroll
            for (int dd = 0; dd < 12; dd++) vv[dd] = Vs[(tx * 12 + dd) * 65 + j];
#pragma unroll
            for (int dd = 0; dd < 12; dd++) {
                o[0][dd] += p0 * vv[dd];
                o[1][dd] += p1 * vv[dd];
                o[2][dd] += p2 * vv[dd];
                o[3][dd] += p3 * vv[dd];
            }
        }
    }

    int b_ = bh >> 4;
    int h_ = bh & 15;
#pragma unroll
    for (int ii = 0; ii < 4; ii++) {
        int i = ty * 4 + ii;
        float inv = 1.f / rowl[i];
        float* dst = g_attn + (size_t)(b_ * SS + i0 + i) * DL + h_ * DH + tx * 12;
#pragma unroll
        for (int dd = 0; dd < 12; dd++) dst[dd] = o[ii][dd] * inv;
    }
}

// ---------------------------------------------------------------------------
// Kernel 5: out = g_attn @ w_o    [4096,3072]@[3072,1024]
// Tile 64x64, TK=32, 256 threads, 4x4 microtile. tx -> n (coalesced writes).
// ---------------------------------------------------------------------------
__global__ void k_out(const float* __restrict__ w_o, float* __restrict__ out) {
    __shared__ float As[32 * 65];
    __shared__ float Bs[32 * 64];

    int tid = threadIdx.x;
    int tx = tid & 15, ty = tid >> 4;
    int m0 = blockIdx.x * 64;
    int n0 = blockIdx.y * 64;

    float acc[4][4];                  // [ii(m)][jj(n)]
#pragma unroll
    for (int i = 0; i < 4; i++)
#pragma unroll
        for (int j = 0; j < 4; j++) acc[i][j] = 0.f;

    for (int k0 = 0; k0 < DL; k0 += 32) {
        __syncthreads();
        for (int i = tid; i < 64 * 32; i += 256) {
            int m = i >> 5, kk = i & 31;
            As[kk * 65 + m] = g_attn[(size_t)(m0 + m) * DL + k0 + kk];
        }
        for (int i = tid; i < 32 * 64; i += 256) {
            int kk = i >> 6, n = i & 63;
            Bs[kk * 64 + n] = w_o[(size_t)(k0 + kk) * DM + n0 + n];
        }
        __syncthreads();

#pragma unroll 8
        for (int kk = 0; kk < 32; kk++) {
            float a0 = As[kk * 65 + ty * 4 + 0];
            float a1 = As[kk * 65 + ty * 4 + 1];
            float a2 = As[kk * 65 + ty * 4 + 2];
            float a3 = As[kk * 65 + ty * 4 + 3];
            float4 b = *(const float4*)&Bs[kk * 64 + tx * 4];
            acc[0][0] += a0 * b.x; acc[0][1] += a0 * b.y; acc[0][2] += a0 * b.z; acc[0][3] += a0 * b.w;
            acc[1][0] += a1 * b.x; acc[1][1] += a1 * b.y; acc[1][2] += a1 * b.z; acc[1][3] += a1 * b.w;
            acc[2][0] += a2 * b.x; acc[2][1] += a2 * b.y; acc[2][2] += a2 * b.z; acc[2][3] += a2 * b.w;
            acc[3][0] += a3 * b.x; acc[3][1] += a3 * b.y; acc[3][2] += a3 * b.z; acc[3][3] += a3 * b.w;
        }
    }

#pragma unroll
    for (int ii = 0; ii < 4; ii++) {
        float4 v4 = make_float4(acc[ii][0], acc[ii][1], acc[ii][2], acc[ii][3]);
        *(float4*)&out[(size_t)(m0 + ty * 4 + ii) * DM + n0 + tx * 4] = v4;
    }
}

// ---------------------------------------------------------------------------
extern "C" void kernel_launch(void* const* d_in, const int* in_sizes, int n_in,
                              void* d_out, int out_size) {
    (void)in_sizes; (void)n_in; (void)out_size;
    const float* x      = (const float*)d_in[0];
    // d_in[1] = mask (int32 tril) — causality applied analytically, ignored
    const float* w_down = (const float*)d_in[2];
    const float* rms_w  = (const float*)d_in[3];
    const float* w_up   = (const float*)d_in[4];
    const float* w_o    = (const float*)d_in[5];
    float* out = (float*)d_out;

    cudaFuncSetAttribute(k_down_rms, cudaFuncAttributeMaxDynamicSharedMemorySize, 77888);
    cudaFuncSetAttribute(k_qkv,      cudaFuncAttributeMaxDynamicSharedMemorySize, 101376);
    cudaFuncSetAttribute(k_attn,     cudaFuncAttributeMaxDynamicSharedMemorySize, 166400);

    k_down_rms<<<256, 192, 77888>>>(x, w_down, rms_w);
    k_qkv<<<dim3(64, 144), 256, 101376>>>(w_up);
    k_rope<<<dim3(8, 16, 64), 256>>>();
    k_attn<<<dim3(32, 32), 256, 166400>>>();
    k_out<<<dim3(64, 16), 256>>>(w_o, out);
}